// round 15
// baseline (speedup 1.0000x reference)
#include <cuda_runtime.h>
#include <cuda_bf16.h>
#include <math.h>

#define TPB   256
#define NBLK  592                     // K1: 4 blocks/SM * 148 SMs -> all resident
#define GT    (NBLK * TPB)

// ---------------- scratch (static device globals; no allocation) ----------------
__device__ float g_t0A[2][786432];   // stage0 W-resized
__device__ float g_t0B[2][196608];   // stage0 WH-resized
__device__ float g_r0[2][49152];     // stage0 resized [tensor][B=4][3][4096]
__device__ float g_t1A[2][393216];   // stage1 W-resized
__device__ float g_t1B[2][49152];    // stage1 WH-resized
__device__ float g_r1[2][6144];      // stage1 resized [tensor][B=4][3][512]
__device__ unsigned long long g_k0[16384];  // stage0 argmin keys [B][4096]
__device__ unsigned long long g_k1[2048];   // stage1 argmin keys [B][512]
__device__ double g_acc[2];          // per-stage cos sums
__device__ unsigned g_bar;           // K1 barrier arrival counter (self-resets)
__device__ unsigned g_gen;           // K1 barrier generation (monotone across replays)
__device__ unsigned g_done;          // cos completion counter (reset each run)

// ---------------- grid-wide barrier for K1 (all NBLK blocks resident) -----------
__device__ __forceinline__ void grid_sync() {
    __syncthreads();
    if (threadIdx.x == 0) {
        __threadfence();
        unsigned gen = *(volatile unsigned*)&g_gen;
        if (atomicAdd(&g_bar, 1u) == NBLK - 1u) {
            atomicExch(&g_bar, 0u);
            __threadfence();
            atomicAdd(&g_gen, 1u);                // release
        } else {
            while (*(volatile unsigned*)&g_gen == gen) __nanosleep(64);
        }
        __threadfence();
    }
    __syncthreads();
}

// ---------------- table-driven resize tap loop -----------------------------------
// Pre-normalized triangle weights (w/sum_w), matching jax compute_weight_mat
// (kernel_scale R = 64/Lout, half-pixel centers, normalization over in-range taps).
template<int NT>
__device__ __forceinline__ float resize_tab(const float* __restrict__ src, int inner,
                                            const float* __restrict__ w, int jlo)
{
    const float* p = src + (size_t)jlo * inner;
    float acc = 0.0f;
#pragma unroll
    for (int k = 0; k < NT; ++k)
        acc = fmaf(w[k], p[(size_t)k * inner], acc);
    return acc;
}

// ================= K1: persistent flat resize (3 table-driven passes) ===========
__global__ void __launch_bounds__(TPB, 4)
resize_kernel(const float* __restrict__ cs, const float* __restrict__ ct)
{
    __shared__ float s_w0[16 * 8];    // stage0 weights [i][k], prenormalized
    __shared__ float s_w1[8 * 16];    // stage1 weights [i][k]
    __shared__ int   s_j0[16], s_j1[8];
    const int gid = blockIdx.x * TPB + threadIdx.x;

    // ---- weight tables (once per block; shared by all 3 passes) ----
    if (threadIdx.x < 24) {
        int stage = threadIdx.x >= 16;
        int i = stage ? threadIdx.x - 16 : threadIdx.x;
        float R    = stage ? 8.0f : 4.0f;
        float invR = stage ? 0.125f : 0.25f;
        int NT     = stage ? 16 : 8;
        float sf = (i + 0.5f) * R - 0.5f;
        int jlo = (int)floorf(sf - R) + 1;
        if (jlo < 0) jlo = 0;
        if (jlo > 64 - NT) jlo = 64 - NT;
        float wv[16]; float ws = 0.0f;
        for (int k = 0; k < NT; ++k) {
            float w = 1.0f - fabsf((float)(jlo + k) - sf) * invR;
            w = fmaxf(w, 0.0f);
            ws += w; wv[k] = w;
        }
        for (int k = 0; k < NT; ++k) {
            float wn = wv[k] / ws;
            if (stage) s_w1[i * 16 + k] = wn; else s_w0[i * 8 + k] = wn;
        }
        if (stage) s_j1[i] = jlo; else s_j0[i] = jlo;
    }

    // ---- init keys / accumulators (overlaps; independent of resize) ----
    for (int i = gid; i < 16384; i += GT) g_k0[i] = ~0ULL;
    for (int i = gid; i < 2048;  i += GT) g_k1[i] = ~0ULL;
    if (gid < 2) g_acc[gid] = 0.0;
    if (gid == 0) g_done = 0u;
    __syncthreads();                    // weight tables ready

    // ---- pass 1: resize W (innermost) ----
    {
        const int S0 = 786432, S1 = 393216;          // per tensor
        for (int idx = gid; idx < 2 * S0 + 2 * S1; idx += GT) {
            if (idx < 2 * S0) {
                int tensor = idx / S0, l = idx - tensor * S0;
                int i = l & 15, o = l >> 4;
                const float* in = (tensor ? ct : cs) + (size_t)o * 64;
                g_t0A[tensor][l] = resize_tab<8>(in, 1, s_w0 + i * 8, s_j0[i]);
            } else {
                int r = idx - 2 * S0;
                int tensor = r / S1, l = r - tensor * S1;
                int i = l & 7, o = l >> 3;
                const float* in = (tensor ? ct : cs) + (size_t)o * 64;
                g_t1A[tensor][l] = resize_tab<16>(in, 1, s_w1 + i * 16, s_j1[i]);
            }
        }
    }
    grid_sync();

    // ---- pass 2: resize H ----
    {
        const int S0 = 196608, S1 = 49152;
        for (int idx = gid; idx < 2 * S0 + 2 * S1; idx += GT) {
            if (idx < 2 * S0) {
                int tensor = idx / S0, l = idx - tensor * S0;
                int t = l & 15, i = (l >> 4) & 15, o = l >> 8;
                const float* in = g_t0A[tensor] + (size_t)o * 64 * 16 + t;
                g_t0B[tensor][l] = resize_tab<8>(in, 16, s_w0 + i * 8, s_j0[i]);
            } else {
                int r = idx - 2 * S0;
                int tensor = r / S1, l = r - tensor * S1;
                int t = l & 7, i = (l >> 3) & 7, o = l >> 6;
                const float* in = g_t1A[tensor] + (size_t)o * 64 * 8 + t;
                g_t1B[tensor][l] = resize_tab<16>(in, 8, s_w1 + i * 16, s_j1[i]);
            }
        }
    }
    grid_sync();

    // ---- pass 3: resize D ----
    {
        const int S0 = 49152, S1 = 6144;
        for (int idx = gid; idx < 2 * S0 + 2 * S1; idx += GT) {
            if (idx < 2 * S0) {
                int tensor = idx / S0, l = idx - tensor * S0;
                int t = l & 255, i = (l >> 8) & 15, o = l >> 12;
                const float* in = g_t0B[tensor] + (size_t)o * 64 * 256 + t;
                g_r0[tensor][l] = resize_tab<8>(in, 256, s_w0 + i * 8, s_j0[i]);
            } else {
                int r = idx - 2 * S0;
                int tensor = r / S1, l = r - tensor * S1;
                int t = l & 63, i = (l >> 6) & 7, o = l >> 9;
                const float* in = g_t1B[tensor] + (size_t)o * 64 * 64 + t;
                g_r1[tensor][l] = resize_tab<16>(in, 64, s_w1 + i * 16, s_j1[i]);
            }
        }
    }
}

// ================= K2: standalone nearest neighbor (packed fminf argmin) ========
// score = 0.5*|b|^2 - a.b (argmin-equivalent to |a-b|^2). Within a tile, 7 low
// mantissa bits carry the tile-local index and fminf tracks the min (5 instr/
// pair, no select chain). Cross-tile merge via atomicMin on
// (sortable float bits << 32) | m; lower m wins ties (jnp.argmin semantics).
template<int N, int NPT, int NM>
__device__ __forceinline__ void nn_unit(const float* __restrict__ A,
                                        const float* __restrict__ Bp,
                                        unsigned long long* __restrict__ keys,
                                        int b, int ytile, int mtile, float4* sB)
{
    int m0 = mtile * NM;
    const float* bx = Bp + (size_t)b * 3 * N;
    for (int i = threadIdx.x; i < NM; i += TPB) {
        int m = m0 + i;
        float x = bx[m], y = bx[N + m], z = bx[2 * N + m];
        sB[i] = make_float4(x, y, z, 0.5f * (x * x + y * y + z * z));
    }
    __syncthreads();

    const float* ax = A + (size_t)b * 3 * N;
    int nb = ytile * (TPB * NPT) + threadIdx.x;

    float px[NPT], py[NPT], pz[NPT], best[NPT];
#pragma unroll
    for (int k = 0; k < NPT; ++k) {
        int n = nb + k * TPB;
        px[k] = ax[n]; py[k] = ax[N + n]; pz[k] = ax[2 * N + n];
        best[k] = 3.402823466e38f;
    }

#pragma unroll 4
    for (int i = 0; i < NM; ++i) {
        float4 q = sB[i];
#pragma unroll
        for (int k = 0; k < NPT; ++k) {
            float s = fmaf(-px[k], q.x, q.w);
            s = fmaf(-py[k], q.y, s);
            s = fmaf(-pz[k], q.z, s);
            unsigned us = (__float_as_uint(s) & 0xFFFFFF80u) | (unsigned)i;  // LOP3
            best[k] = fminf(best[k], __uint_as_float(us));                    // FMNMX
        }
    }

#pragma unroll
    for (int k = 0; k < NPT; ++k) {
        int n = nb + k * TPB;
        unsigned u = __float_as_uint(best[k]);
        int i = (int)(u & 0x7Fu);
        unsigned su = (u & 0x80000000u) ? ~u : (u | 0x80000000u);  // order-preserving
        unsigned long long key = ((unsigned long long)su << 32) | (unsigned)(m0 + i);
        atomicMin(&keys[(size_t)b * N + n], key);
    }
}

// grid 544: u<512 -> stage0 (b(4) x ytile(4) x mtile(32), NM=128, NPT=4);
//           else  -> stage1 (b(4) x mtile(8), NM=64, NPT=2)
__global__ void nn_kernel()
{
    __shared__ float4 sB[128];
    int u = blockIdx.x;
    if (u < 512) {
        nn_unit<4096, 4, 128>(g_r0[0], g_r0[1], g_k0,
                              u & 3, (u >> 2) & 3, u >> 4, sB);
    } else {
        int v = u - 512;
        nn_unit<512, 2, 64>(g_r1[0], g_r1[1], g_k1,
                            v & 3, 0, v >> 2, sB);
    }
}

// ================= K3: cosine + reduction + in-kernel finalize ==================
// desc layout [B][32][N]; flattened-spatial element (b,n,c) = desc[b,c,n].
template<int N>
__device__ __forceinline__ float cos_body(const float* __restrict__ sd,
                                          const float* __restrict__ td,
                                          const unsigned long long* __restrict__ keys,
                                          int b, int xb)
{
    int n = xb * TPB + threadIdx.x;
    int m = (int)(unsigned)(keys[(size_t)b * N + n] & 0xFFFFFFFFull);

    const float* s = sd + (size_t)b * 32 * N;
    const float* t = td + (size_t)b * 32 * N;
    float dot = 0.f, ns = 0.f, ng = 0.f;
#pragma unroll
    for (int c = 0; c < 32; ++c) {
        float x = s[(size_t)c * N + n];
        float y = t[(size_t)c * N + m];
        dot = fmaf(x, y, dot);
        ns  = fmaf(x, x, ns);
        ng  = fmaf(y, y, ng);
    }
    return dot / (fmaxf(sqrtf(ns), 1e-8f) * fmaxf(sqrtf(ng), 1e-8f));
}

// grid 72: u<64 -> stage0 (b(4) x xb(16)); else stage1 (b(4) x xb(2))
__global__ void cos_kernel(const float* __restrict__ sd0, const float* __restrict__ td0,
                           const float* __restrict__ sd1, const float* __restrict__ td1,
                           float* __restrict__ out)
{
    __shared__ float wsum[TPB / 32];
    int u = blockIdx.x;
    int stage = (u < 64) ? 0 : 1;
    float cv;
    if (stage == 0) cv = cos_body<4096>(sd0, td0, g_k0, u & 3, u >> 2);
    else            cv = cos_body<512> (sd1, td1, g_k1, (u - 64) & 3, (u - 64) >> 2);

    for (int o = 16; o > 0; o >>= 1) cv += __shfl_down_sync(0xffffffffu, cv, o);
    if ((threadIdx.x & 31) == 0) wsum[threadIdx.x >> 5] = cv;
    __syncthreads();
    if (threadIdx.x < TPB / 32) {
        float v = wsum[threadIdx.x];
        for (int o = (TPB / 64); o > 0; o >>= 1) v += __shfl_down_sync(0xffu, v, o);
        if (threadIdx.x == 0) {
            atomicAdd(&g_acc[stage], (double)v);
            __threadfence();
            if (atomicAdd(&g_done, 1u) == 71u) {          // last cos block
                double a0 = atomicAdd(&g_acc[0], 0.0);
                double a1 = atomicAdd(&g_acc[1], 0.0);
                double l0 = 1.0 - a0 / (4.0 * 4096.0);
                double l1 = 1.0 - a1 / (4.0 * 512.0);
                out[0] = (float)(0.5 * (l0 + l1));
            }
        }
    }
}

// ---------------- launch (3 kernel launches) -------------------------------------
extern "C" void kernel_launch(void* const* d_in, const int* in_sizes, int n_in,
                              void* d_out, int out_size)
{
    const float* cs  = (const float*)d_in[0];  // canonical_source [4,3,64,64,64]
    const float* ct  = (const float*)d_in[1];  // canonical_target
    const float* sd0 = (const float*)d_in[2];  // src_desc0 [4,32,16,16,16]
    const float* td0 = (const float*)d_in[3];
    const float* sd1 = (const float*)d_in[4];  // src_desc1 [4,32,8,8,8]
    const float* td1 = (const float*)d_in[5];
    float* out = (float*)d_out;

    resize_kernel<<<NBLK, TPB>>>(cs, ct);
    nn_kernel<<<544, TPB>>>();
    cos_kernel<<<72, TPB>>>(sd0, td0, sd1, td1, out);
}

// round 16
// speedup vs baseline: 1.2991x; 1.2991x over previous
#include <cuda_runtime.h>
#include <cuda_bf16.h>
#include <math.h>

#define TPB   256
#define NBLK  592                     // K1: 4 blocks/SM * 148 SMs -> all resident
#define GT    (NBLK * TPB)
#define PAD   65                      // smem row stride (floats): +1 kills 4-way conflicts

// ---------------- scratch (static device globals; no allocation) ----------------
__device__ float g_t0A[2][786432];   // stage0 W-resized [tensor][o*16+i]
__device__ float g_t0B[2][196608];   // stage0 WH-resized
__device__ float g_r0[2][49152];     // stage0 resized [tensor][B=4][3][4096]
__device__ float g_t1A[2][393216];   // stage1 W-resized [tensor][o*8+i]
__device__ float g_t1B[2][49152];    // stage1 WH-resized
__device__ float g_r1[2][6144];      // stage1 resized [tensor][B=4][3][512]
__device__ unsigned long long g_k0[16384];  // stage0 argmin keys [B][4096]
__device__ unsigned long long g_k1[2048];   // stage1 argmin keys [B][512]
__device__ double g_acc[2];          // per-stage cos sums
__device__ unsigned g_bar;           // K1 barrier arrival counter (self-resets)
__device__ unsigned g_gen;           // K1 barrier generation (monotone across replays)
__device__ unsigned g_done;          // cos completion counter (reset each run)

// ---------------- grid-wide barrier for K1 (all NBLK blocks resident) -----------
__device__ __forceinline__ void grid_sync() {
    __syncthreads();
    if (threadIdx.x == 0) {
        __threadfence();
        unsigned gen = *(volatile unsigned*)&g_gen;
        if (atomicAdd(&g_bar, 1u) == NBLK - 1u) {
            atomicExch(&g_bar, 0u);
            __threadfence();
            atomicAdd(&g_gen, 1u);                // release
        } else {
            while (*(volatile unsigned*)&g_gen == gen) __nanosleep(64);
        }
        __threadfence();
    }
    __syncthreads();
}

// ---------------- table-driven resize tap loop (passes 2/3) ---------------------
template<int NT>
__device__ __forceinline__ float resize_tab(const float* __restrict__ src, int inner,
                                            const float* __restrict__ w, int jlo)
{
    const float* p = src + (size_t)jlo * inner;
    float acc = 0.0f;
#pragma unroll
    for (int k = 0; k < NT; ++k)
        acc = fmaf(w[k], p[(size_t)k * inner], acc);
    return acc;
}

// ================= K1: persistent resize =========================================
// jax triangle antialias: kernel_scale R = 64/Lout, half-pixel centers,
// pre-normalized weights over in-range taps (== compute_weight_mat).
// Pass 1 (W, inner=1) is smem-staged per 32-row unit with coalesced float4 global
// reads; passes 2/3 are flat (inner>=8 -> sector-coalesced).
__global__ void __launch_bounds__(TPB, 4)
resize_kernel(const float* __restrict__ cs, const float* __restrict__ ct)
{
    __shared__ float s_in[32 * PAD];  // staged rows (8.3KB)
    __shared__ float s_w0[16 * 8];    // stage0 weights [i][k], prenormalized
    __shared__ float s_w1[8 * 16];    // stage1 weights [i][k]
    __shared__ int   s_j0[16], s_j1[8];
    const int gid = blockIdx.x * TPB + threadIdx.x;
    const int tid = threadIdx.x;

    // ---- weight tables (once per block; shared by all passes) ----
    if (tid < 24) {
        int stage = tid >= 16;
        int i = stage ? tid - 16 : tid;
        float R    = stage ? 8.0f : 4.0f;
        float invR = stage ? 0.125f : 0.25f;
        int NT     = stage ? 16 : 8;
        float sf = (i + 0.5f) * R - 0.5f;
        int jlo = (int)floorf(sf - R) + 1;
        if (jlo < 0) jlo = 0;
        if (jlo > 64 - NT) jlo = 64 - NT;
        float wv[16]; float ws = 0.0f;
        for (int k = 0; k < NT; ++k) {
            float w = 1.0f - fabsf((float)(jlo + k) - sf) * invR;
            w = fmaxf(w, 0.0f);
            ws += w; wv[k] = w;
        }
        for (int k = 0; k < NT; ++k) {
            float wn = wv[k] / ws;
            if (stage) s_w1[i * 16 + k] = wn; else s_w0[i * 8 + k] = wn;
        }
        if (stage) s_j1[i] = jlo; else s_j0[i] = jlo;
    }

    // ---- init keys / accumulators (independent of resize; overlaps) ----
    for (int i = gid; i < 16384; i += GT) g_k0[i] = ~0ULL;
    for (int i = gid; i < 2048;  i += GT) g_k1[i] = ~0ULL;
    if (gid < 2) g_acc[gid] = 0.0;
    if (gid == 0) g_done = 0u;
    __syncthreads();                    // tables ready

    // ---- hoist this thread's weights/jlo into registers (fixed output column) ----
    const int i0 = tid & 15;            // stage0 output column (outputs tid, tid+256)
    const int i1 = tid & 7;             // stage1 output column
    const int r0 = tid >> 4;            // stage0 row (0..15; +16 for second output)
    const int r1 = tid >> 3;            // stage1 row (0..31)
    float w0r[8], w1r[16];
#pragma unroll
    for (int k = 0; k < 8; ++k)  w0r[k] = s_w0[i0 * 8 + k];
#pragma unroll
    for (int k = 0; k < 16; ++k) w1r[k] = s_w1[i1 * 16 + k];
    const int jlo0 = s_j0[i0];
    const int jlo1 = s_j1[i1];

    // ---- pass 1: W-resize, both stages, smem-staged 32-row units ----
    // rows: [2 tensors][49152 rows][64]; 3072 units of 32 rows (units never
    // straddle tensors: 49152 = 1536*32).
    for (int u = blockIdx.x; u < 3072; u += NBLK) {
        int tensor = u >> 11;                    // u / 1536... careful: 1536*2=3072
        tensor = (u >= 1536) ? 1 : 0;
        int rbase = (u - tensor * 1536) * 32;    // local row base within tensor
        const float4* src4 = (const float4*)((tensor ? ct : cs) + (size_t)rbase * 64);

        __syncthreads();                         // previous unit's readers done
        // stage 32 rows (2048 floats = 512 float4), padded layout
#pragma unroll
        for (int v = tid; v < 512; v += TPB) {
            float4 q = src4[v];
            int r = v >> 4, c = (v & 15) << 2;
            float* d = s_in + r * PAD + c;
            d[0] = q.x; d[1] = q.y; d[2] = q.z; d[3] = q.w;
        }
        __syncthreads();

        // stage0: outputs (r0, i0) and (r0+16, i0)
        float a0 = 0.0f, a1 = 0.0f;
        const float* p0 = s_in + r0 * PAD + jlo0;
        const float* p1 = p0 + 16 * PAD;
#pragma unroll
        for (int k = 0; k < 8; ++k) {
            a0 = fmaf(w0r[k], p0[k], a0);
            a1 = fmaf(w0r[k], p1[k], a1);
        }
        g_t0A[tensor][(rbase + r0) * 16 + i0]      = a0;
        g_t0A[tensor][(rbase + r0 + 16) * 16 + i0] = a1;

        // stage1: output (r1, i1)
        float b = 0.0f;
        const float* p2 = s_in + r1 * PAD + jlo1;
#pragma unroll
        for (int k = 0; k < 16; ++k)
            b = fmaf(w1r[k], p2[k], b);
        g_t1A[tensor][(rbase + r1) * 8 + i1] = b;
    }
    grid_sync();

    // ---- pass 2: H-resize (flat; inner>=8 -> coalesced sectors) ----
    {
        const int S0 = 196608, S1 = 49152;
        for (int idx = gid; idx < 2 * S0 + 2 * S1; idx += GT) {
            if (idx < 2 * S0) {
                int tensor = idx / S0, l = idx - tensor * S0;
                int t = l & 15, i = (l >> 4) & 15, o = l >> 8;
                const float* in = g_t0A[tensor] + (size_t)o * 64 * 16 + t;
                g_t0B[tensor][l] = resize_tab<8>(in, 16, s_w0 + i * 8, s_j0[i]);
            } else {
                int r = idx - 2 * S0;
                int tensor = r / S1, l = r - tensor * S1;
                int t = l & 7, i = (l >> 3) & 7, o = l >> 6;
                const float* in = g_t1A[tensor] + (size_t)o * 64 * 8 + t;
                g_t1B[tensor][l] = resize_tab<16>(in, 8, s_w1 + i * 16, s_j1[i]);
            }
        }
    }
    grid_sync();

    // ---- pass 3: D-resize (flat) ----
    {
        const int S0 = 49152, S1 = 6144;
        for (int idx = gid; idx < 2 * S0 + 2 * S1; idx += GT) {
            if (idx < 2 * S0) {
                int tensor = idx / S0, l = idx - tensor * S0;
                int t = l & 255, i = (l >> 8) & 15, o = l >> 12;
                const float* in = g_t0B[tensor] + (size_t)o * 64 * 256 + t;
                g_r0[tensor][l] = resize_tab<8>(in, 256, s_w0 + i * 8, s_j0[i]);
            } else {
                int r = idx - 2 * S0;
                int tensor = r / S1, l = r - tensor * S1;
                int t = l & 63, i = (l >> 6) & 7, o = l >> 9;
                const float* in = g_t1B[tensor] + (size_t)o * 64 * 64 + t;
                g_r1[tensor][l] = resize_tab<16>(in, 64, s_w1 + i * 16, s_j1[i]);
            }
        }
    }
}

// ================= K2: standalone nearest neighbor (packed fminf argmin) ========
// score = 0.5*|b|^2 - a.b (argmin-equivalent to |a-b|^2). Within a tile, 7 low
// mantissa bits carry the tile-local index and fminf tracks the min. Cross-tile
// merge via atomicMin on (sortable float bits << 32) | m; lower m wins ties
// (jnp.argmin first-occurrence semantics).
template<int N, int NPT, int NM>
__device__ __forceinline__ void nn_unit(const float* __restrict__ A,
                                        const float* __restrict__ Bp,
                                        unsigned long long* __restrict__ keys,
                                        int b, int ytile, int mtile, float4* sB)
{
    int m0 = mtile * NM;
    const float* bx = Bp + (size_t)b * 3 * N;
    for (int i = threadIdx.x; i < NM; i += TPB) {
        int m = m0 + i;
        float x = bx[m], y = bx[N + m], z = bx[2 * N + m];
        sB[i] = make_float4(x, y, z, 0.5f * (x * x + y * y + z * z));
    }
    __syncthreads();

    const float* ax = A + (size_t)b * 3 * N;
    int nb = ytile * (TPB * NPT) + threadIdx.x;

    float px[NPT], py[NPT], pz[NPT], best[NPT];
#pragma unroll
    for (int k = 0; k < NPT; ++k) {
        int n = nb + k * TPB;
        px[k] = ax[n]; py[k] = ax[N + n]; pz[k] = ax[2 * N + n];
        best[k] = 3.402823466e38f;
    }

#pragma unroll 4
    for (int i = 0; i < NM; ++i) {
        float4 q = sB[i];
#pragma unroll
        for (int k = 0; k < NPT; ++k) {
            float s = fmaf(-px[k], q.x, q.w);
            s = fmaf(-py[k], q.y, s);
            s = fmaf(-pz[k], q.z, s);
            unsigned us = (__float_as_uint(s) & 0xFFFFFF80u) | (unsigned)i;  // LOP3
            best[k] = fminf(best[k], __uint_as_float(us));                    // FMNMX
        }
    }

#pragma unroll
    for (int k = 0; k < NPT; ++k) {
        int n = nb + k * TPB;
        unsigned u = __float_as_uint(best[k]);
        int i = (int)(u & 0x7Fu);
        unsigned su = (u & 0x80000000u) ? ~u : (u | 0x80000000u);  // order-preserving
        unsigned long long key = ((unsigned long long)su << 32) | (unsigned)(m0 + i);
        atomicMin(&keys[(size_t)b * N + n], key);
    }
}

// grid 544: u<512 -> stage0 (b(4) x ytile(4) x mtile(32), NM=128, NPT=4);
//           else  -> stage1 (b(4) x mtile(8), NM=64, NPT=2)
__global__ void nn_kernel()
{
    __shared__ float4 sB[128];
    int u = blockIdx.x;
    if (u < 512) {
        nn_unit<4096, 4, 128>(g_r0[0], g_r0[1], g_k0,
                              u & 3, (u >> 2) & 3, u >> 4, sB);
    } else {
        int v = u - 512;
        nn_unit<512, 2, 64>(g_r1[0], g_r1[1], g_k1,
                            v & 3, 0, v >> 2, sB);
    }
}

// ================= K3: cosine + reduction + in-kernel finalize ==================
// desc layout [B][32][N]; flattened-spatial element (b,n,c) = desc[b,c,n].
template<int N>
__device__ __forceinline__ float cos_body(const float* __restrict__ sd,
                                          const float* __restrict__ td,
                                          const unsigned long long* __restrict__ keys,
                                          int b, int xb)
{
    int n = xb * TPB + threadIdx.x;
    int m = (int)(unsigned)(keys[(size_t)b * N + n] & 0xFFFFFFFFull);

    const float* s = sd + (size_t)b * 32 * N;
    const float* t = td + (size_t)b * 32 * N;
    float dot = 0.f, ns = 0.f, ng = 0.f;
#pragma unroll
    for (int c = 0; c < 32; ++c) {
        float x = s[(size_t)c * N + n];
        float y = t[(size_t)c * N + m];
        dot = fmaf(x, y, dot);
        ns  = fmaf(x, x, ns);
        ng  = fmaf(y, y, ng);
    }
    return dot / (fmaxf(sqrtf(ns), 1e-8f) * fmaxf(sqrtf(ng), 1e-8f));
}

// grid 72: u<64 -> stage0 (b(4) x xb(16)); else stage1 (b(4) x xb(2))
__global__ void cos_kernel(const float* __restrict__ sd0, const float* __restrict__ td0,
                           const float* __restrict__ sd1, const float* __restrict__ td1,
                           float* __restrict__ out)
{
    __shared__ float wsum[TPB / 32];
    int u = blockIdx.x;
    int stage = (u < 64) ? 0 : 1;
    float cv;
    if (stage == 0) cv = cos_body<4096>(sd0, td0, g_k0, u & 3, u >> 2);
    else            cv = cos_body<512> (sd1, td1, g_k1, (u - 64) & 3, (u - 64) >> 2);

    for (int o = 16; o > 0; o >>= 1) cv += __shfl_down_sync(0xffffffffu, cv, o);
    if ((threadIdx.x & 31) == 0) wsum[threadIdx.x >> 5] = cv;
    __syncthreads();
    if (threadIdx.x < TPB / 32) {
        float v = wsum[threadIdx.x];
        for (int o = (TPB / 64); o > 0; o >>= 1) v += __shfl_down_sync(0xffu, v, o);
        if (threadIdx.x == 0) {
            atomicAdd(&g_acc[stage], (double)v);
            __threadfence();
            if (atomicAdd(&g_done, 1u) == 71u) {          // last cos block
                double a0 = atomicAdd(&g_acc[0], 0.0);
                double a1 = atomicAdd(&g_acc[1], 0.0);
                double l0 = 1.0 - a0 / (4.0 * 4096.0);
                double l1 = 1.0 - a1 / (4.0 * 512.0);
                out[0] = (float)(0.5 * (l0 + l1));
            }
        }
    }
}

// ---------------- launch (3 kernel launches) -------------------------------------
extern "C" void kernel_launch(void* const* d_in, const int* in_sizes, int n_in,
                              void* d_out, int out_size)
{
    const float* cs  = (const float*)d_in[0];  // canonical_source [4,3,64,64,64]
    const float* ct  = (const float*)d_in[1];  // canonical_target
    const float* sd0 = (const float*)d_in[2];  // src_desc0 [4,32,16,16,16]
    const float* td0 = (const float*)d_in[3];
    const float* sd1 = (const float*)d_in[4];  // src_desc1 [4,32,8,8,8]
    const float* td1 = (const float*)d_in[5];
    float* out = (float*)d_out;

    resize_kernel<<<NBLK, TPB>>>(cs, ct);
    nn_kernel<<<544, TPB>>>();
    cos_kernel<<<72, TPB>>>(sd0, td0, sd1, td1, out);
}

// round 17
// speedup vs baseline: 2.1151x; 1.6281x over previous
#include <cuda_runtime.h>
#include <cuda_bf16.h>
#include <math.h>

#define TPB   256
#define NBLK  592                     // K1: 4 blocks/SM * 148 SMs -> all resident
#define GT    (NBLK * TPB)
#define PAD   65                      // smem row stride (floats)

// ---------------- scratch (static device globals; no allocation) ----------------
__device__ float g_t0A[2][786432];   // stage0 W-resized [tensor][o*16+i]
__device__ float g_t0B[2][196608];   // stage0 WH-resized
__device__ float g_r0[2][49152];     // stage0 resized [tensor][B=4][3][4096]
__device__ float g_t1A[2][393216];   // stage1 W-resized [tensor][o*8+i]
__device__ float g_t1B[2][49152];    // stage1 WH-resized
__device__ float g_r1[2][6144];      // stage1 resized [tensor][B=4][3][512]
__device__ unsigned long long g_k0[16384];  // stage0 argmin keys [B][4096]
__device__ unsigned long long g_k1[2048];   // stage1 argmin keys [B][512]
__device__ double g_acc[2];          // per-stage cos sums
__device__ unsigned g_bar;           // K1 barrier arrival counter (self-resets)
__device__ unsigned g_gen;           // K1 barrier generation (monotone across replays)
__device__ unsigned g_done;          // cos completion counter (reset each run)

// ---------------- grid-wide barrier for K1 (all NBLK blocks resident) -----------
__device__ __forceinline__ void grid_sync() {
    __syncthreads();
    if (threadIdx.x == 0) {
        __threadfence();
        unsigned gen = *(volatile unsigned*)&g_gen;
        if (atomicAdd(&g_bar, 1u) == NBLK - 1u) {
            atomicExch(&g_bar, 0u);
            __threadfence();
            atomicAdd(&g_gen, 1u);                // release
        } else {
            while (*(volatile unsigned*)&g_gen == gen) __nanosleep(64);
        }
        __threadfence();
    }
    __syncthreads();
}

// ---------------- packed f32x2 fma ----------------------------------------------
__device__ __forceinline__ unsigned long long fma2(unsigned long long a,
                                                   unsigned long long b,
                                                   unsigned long long c) {
    unsigned long long d;
    asm("fma.rn.f32x2 %0, %1, %2, %3;" : "=l"(d) : "l"(a), "l"(b), "l"(c));
    return d;
}
__device__ __forceinline__ unsigned long long pack2(float lo, float hi) {
    unsigned long long d;
    asm("mov.b64 %0, {%1, %2};" : "=l"(d) : "f"(lo), "f"(hi));
    return d;
}

// ---------------- table-driven resize tap loop (passes 2/3) ---------------------
template<int NT>
__device__ __forceinline__ float resize_tab(const float* __restrict__ src, int inner,
                                            const float* __restrict__ w, int jlo)
{
    const float* p = src + (size_t)jlo * inner;
    float acc = 0.0f;
#pragma unroll
    for (int k = 0; k < NT; ++k)
        acc = fmaf(w[k], p[(size_t)k * inner], acc);
    return acc;
}

// ================= K1: persistent resize =========================================
// jax triangle antialias: kernel_scale R = 64/Lout, half-pixel centers,
// pre-normalized weights over in-range taps (== compute_weight_mat).
// Pass 1 (W) is smem-staged per 32-row unit, DOUBLE-BUFFERED with register
// prefetch of the next unit so DRAM latency overlaps compute.
__global__ void __launch_bounds__(TPB, 4)
resize_kernel(const float* __restrict__ cs, const float* __restrict__ ct)
{
    __shared__ float s_in[2][32 * PAD];  // double-buffered staging (16.6KB)
    __shared__ float s_w0[16 * 8];       // stage0 weights [i][k], prenormalized
    __shared__ float s_w1[8 * 16];       // stage1 weights [i][k]
    __shared__ int   s_j0[16], s_j1[8];
    const int gid = blockIdx.x * TPB + threadIdx.x;
    const int tid = threadIdx.x;

    // ---- weight tables (once per block; shared by all passes) ----
    if (tid < 24) {
        int stage = tid >= 16;
        int i = stage ? tid - 16 : tid;
        float R    = stage ? 8.0f : 4.0f;
        float invR = stage ? 0.125f : 0.25f;
        int NT     = stage ? 16 : 8;
        float sf = (i + 0.5f) * R - 0.5f;
        int jlo = (int)floorf(sf - R) + 1;
        if (jlo < 0) jlo = 0;
        if (jlo > 64 - NT) jlo = 64 - NT;
        float wv[16]; float ws = 0.0f;
        for (int k = 0; k < NT; ++k) {
            float w = 1.0f - fabsf((float)(jlo + k) - sf) * invR;
            w = fmaxf(w, 0.0f);
            ws += w; wv[k] = w;
        }
        for (int k = 0; k < NT; ++k) {
            float wn = wv[k] / ws;
            if (stage) s_w1[i * 16 + k] = wn; else s_w0[i * 8 + k] = wn;
        }
        if (stage) s_j1[i] = jlo; else s_j0[i] = jlo;
    }

    // ---- init keys / accumulators (independent of resize; overlaps) ----
    for (int i = gid; i < 16384; i += GT) g_k0[i] = ~0ULL;
    for (int i = gid; i < 2048;  i += GT) g_k1[i] = ~0ULL;
    if (gid < 2) g_acc[gid] = 0.0;
    if (gid == 0) g_done = 0u;
    __syncthreads();                    // tables ready

    // ---- hoist this thread's weights/jlo into registers ----
    const int i0 = tid & 15;            // stage0 output column
    const int i1 = tid & 7;             // stage1 output column
    const int r0 = tid >> 4;            // stage0 row (0..15; +16 for 2nd output)
    const int r1 = tid >> 3;            // stage1 row (0..31)
    float w0r[8], w1r[16];
#pragma unroll
    for (int k = 0; k < 8; ++k)  w0r[k] = s_w0[i0 * 8 + k];
#pragma unroll
    for (int k = 0; k < 16; ++k) w1r[k] = s_w1[i1 * 16 + k];
    const int jlo0 = s_j0[i0];
    const int jlo1 = s_j1[i1];

    // ---- pass 1: W-resize, 32-row units, double-buffered + prefetch ----
    // rows: [2 tensors][49152 rows][64]; 3072 units (1536 per tensor).
    float4 qa, qb;
    {
        int u = blockIdx.x;
        if (u < 3072) {
            int tensor = (u >= 1536) ? 1 : 0;
            int rbase = (u - tensor * 1536) * 32;
            const float4* s4 = (const float4*)((tensor ? ct : cs) + (size_t)rbase * 64);
            qa = s4[tid]; qb = s4[tid + 256];
        }
    }
    int buf = 0;
    for (int u = blockIdx.x; u < 3072; u += NBLK) {
        int tensor = (u >= 1536) ? 1 : 0;
        int rbase = (u - tensor * 1536) * 32;
        float* dst = s_in[buf];

        // store prefetched unit
        {
            int r = tid >> 4, c = (tid & 15) << 2;
            float* d = dst + r * PAD + c;
            d[0] = qa.x; d[1] = qa.y; d[2] = qa.z; d[3] = qa.w;
            int v2 = tid + 256; r = v2 >> 4; c = (v2 & 15) << 2;
            d = dst + r * PAD + c;
            d[0] = qb.x; d[1] = qb.y; d[2] = qb.z; d[3] = qb.w;
        }
        __syncthreads();

        // prefetch next unit (LDGs in flight during compute below)
        int un = u + NBLK;
        if (un < 3072) {
            int tn = (un >= 1536) ? 1 : 0;
            int rb = (un - tn * 1536) * 32;
            const float4* s4 = (const float4*)((tn ? ct : cs) + (size_t)rb * 64);
            qa = s4[tid]; qb = s4[tid + 256];
        }

        // stage0: outputs (r0, i0) and (r0+16, i0)
        float a0 = 0.0f, a1 = 0.0f;
        const float* p0 = dst + r0 * PAD + jlo0;
        const float* p1 = p0 + 16 * PAD;
#pragma unroll
        for (int k = 0; k < 8; ++k) {
            a0 = fmaf(w0r[k], p0[k], a0);
            a1 = fmaf(w0r[k], p1[k], a1);
        }
        g_t0A[tensor][(rbase + r0) * 16 + i0]      = a0;
        g_t0A[tensor][(rbase + r0 + 16) * 16 + i0] = a1;

        // stage1: output (r1, i1)
        float b = 0.0f;
        const float* p2 = dst + r1 * PAD + jlo1;
#pragma unroll
        for (int k = 0; k < 16; ++k)
            b = fmaf(w1r[k], p2[k], b);
        g_t1A[tensor][(rbase + r1) * 8 + i1] = b;

        buf ^= 1;
    }
    grid_sync();

    // ---- pass 2: H-resize (flat; inner>=8 -> coalesced sectors) ----
    {
        const int S0 = 196608, S1 = 49152;
        for (int idx = gid; idx < 2 * S0 + 2 * S1; idx += GT) {
            if (idx < 2 * S0) {
                int tensor = idx / S0, l = idx - tensor * S0;
                int t = l & 15, i = (l >> 4) & 15, o = l >> 8;
                const float* in = g_t0A[tensor] + (size_t)o * 64 * 16 + t;
                g_t0B[tensor][l] = resize_tab<8>(in, 16, s_w0 + i * 8, s_j0[i]);
            } else {
                int r = idx - 2 * S0;
                int tensor = r / S1, l = r - tensor * S1;
                int t = l & 7, i = (l >> 3) & 7, o = l >> 6;
                const float* in = g_t1A[tensor] + (size_t)o * 64 * 8 + t;
                g_t1B[tensor][l] = resize_tab<16>(in, 8, s_w1 + i * 16, s_j1[i]);
            }
        }
    }
    grid_sync();

    // ---- pass 3: D-resize (flat) ----
    {
        const int S0 = 49152, S1 = 6144;
        for (int idx = gid; idx < 2 * S0 + 2 * S1; idx += GT) {
            if (idx < 2 * S0) {
                int tensor = idx / S0, l = idx - tensor * S0;
                int t = l & 255, i = (l >> 8) & 15, o = l >> 12;
                const float* in = g_t0B[tensor] + (size_t)o * 64 * 256 + t;
                g_r0[tensor][l] = resize_tab<8>(in, 256, s_w0 + i * 8, s_j0[i]);
            } else {
                int r = idx - 2 * S0;
                int tensor = r / S1, l = r - tensor * S1;
                int t = l & 63, i = (l >> 6) & 7, o = l >> 9;
                const float* in = g_t1B[tensor] + (size_t)o * 64 * 64 + t;
                g_r1[tensor][l] = resize_tab<16>(in, 64, s_w1 + i * 16, s_j1[i]);
            }
        }
    }
}

// ================= K2: nearest neighbor (f32x2 dual-candidate fminf argmin) =====
// score = 0.5*|b|^2 - a.b (argmin-equivalent to |a-b|^2). Each m-tile is split
// into lo ([0,H)) and hi ([H,2H)) halves; 3 fma.rn.f32x2 evaluate both halves'
// candidate i at once. 7 low mantissa bits carry i; fminf tracks each half's
// min. Merge builds both full 64-bit keys ((sortable bits << 32) | m) and
// atomicMin's the smaller -> lower m wins ties (jnp.argmin first-occurrence).
template<int N, int NPT, int NM>
__device__ __forceinline__ void nn_unit(const float* __restrict__ A,
                                        const float* __restrict__ Bp,
                                        unsigned long long* __restrict__ keys,
                                        int b, int ytile, int mtile,
                                        float4* sXY, float4* sZW)
{
    const int H = NM / 2;
    int m0 = mtile * NM;
    const float* bx = Bp + (size_t)b * 3 * N;
    for (int i = threadIdx.x; i < H; i += TPB) {
        int ml = m0 + i, mh = ml + H;
        float xl = bx[ml], yl = bx[N + ml], zl = bx[2 * N + ml];
        float xh = bx[mh], yh = bx[N + mh], zh = bx[2 * N + mh];
        sXY[i] = make_float4(xl, xh, yl, yh);
        sZW[i] = make_float4(zl, zh,
                             0.5f * (xl * xl + yl * yl + zl * zl),
                             0.5f * (xh * xh + yh * yh + zh * zh));
    }
    __syncthreads();

    const float* ax = A + (size_t)b * 3 * N;
    int nb = ytile * (TPB * NPT) + threadIdx.x;

    unsigned long long npx[NPT], npy[NPT], npz[NPT];
    float best_lo[NPT], best_hi[NPT];
#pragma unroll
    for (int k = 0; k < NPT; ++k) {
        int n = nb + k * TPB;
        float x = ax[n], y = ax[N + n], z = ax[2 * N + n];
        npx[k] = pack2(-x, -x); npy[k] = pack2(-y, -y); npz[k] = pack2(-z, -z);
        best_lo[k] = 3.402823466e38f; best_hi[k] = 3.402823466e38f;
    }

#pragma unroll 2
    for (int i = 0; i < H; ++i) {
        ulonglong2 xy = *reinterpret_cast<const ulonglong2*>(&sXY[i]);  // x2, y2
        ulonglong2 zw = *reinterpret_cast<const ulonglong2*>(&sZW[i]);  // z2, w2
#pragma unroll
        for (int k = 0; k < NPT; ++k) {
            unsigned long long s2 = fma2(npx[k], xy.x,
                                   fma2(npy[k], xy.y,
                                   fma2(npz[k], zw.x, zw.y)));
            unsigned lo = (unsigned)s2, hi = (unsigned)(s2 >> 32);
            unsigned ul = (lo & 0xFFFFFF80u) | (unsigned)i;
            unsigned uh = (hi & 0xFFFFFF80u) | (unsigned)i;
            best_lo[k] = fminf(best_lo[k], __uint_as_float(ul));
            best_hi[k] = fminf(best_hi[k], __uint_as_float(uh));
        }
    }

#pragma unroll
    for (int k = 0; k < NPT; ++k) {
        int n = nb + k * TPB;
        unsigned a = __float_as_uint(best_lo[k]);
        unsigned c = __float_as_uint(best_hi[k]);
        unsigned ia = a & 0x7Fu, ic = (c & 0x7Fu) + (unsigned)H;
        unsigned sa = (a & 0x80000000u) ? ~a : (a | 0x80000000u);
        unsigned sc = (c & 0x80000000u) ? ~c : (c | 0x80000000u);
        unsigned long long ka = ((unsigned long long)sa << 32) | (unsigned)(m0 + ia);
        unsigned long long kc = ((unsigned long long)sc << 32) | (unsigned)(m0 + ic);
        unsigned long long key = (ka < kc) ? ka : kc;
        atomicMin(&keys[(size_t)b * N + n], key);
    }
}

// grid 544: u<512 -> stage0 (b(4) x ytile(4) x mtile(32), NM=128, NPT=4);
//           else  -> stage1 (b(4) x mtile(8), NM=64, NPT=2)
__global__ void nn_kernel()
{
    __shared__ float4 sXY[64];
    __shared__ float4 sZW[64];
    int u = blockIdx.x;
    if (u < 512) {
        nn_unit<4096, 4, 128>(g_r0[0], g_r0[1], g_k0,
                              u & 3, (u >> 2) & 3, u >> 4, sXY, sZW);
    } else {
        int v = u - 512;
        nn_unit<512, 2, 64>(g_r1[0], g_r1[1], g_k1,
                            v & 3, 0, v >> 2, sXY, sZW);
    }
}

// ================= K3: cosine + reduction + in-kernel finalize ==================
// desc layout [B][32][N]; flattened-spatial element (b,n,c) = desc[b,c,n].
template<int N>
__device__ __forceinline__ float cos_body(const float* __restrict__ sd,
                                          const float* __restrict__ td,
                                          const unsigned long long* __restrict__ keys,
                                          int b, int xb)
{
    int n = xb * TPB + threadIdx.x;
    int m = (int)(unsigned)(keys[(size_t)b * N + n] & 0xFFFFFFFFull);

    const float* s = sd + (size_t)b * 32 * N;
    const float* t = td + (size_t)b * 32 * N;
    float dot = 0.f, ns = 0.f, ng = 0.f;
#pragma unroll
    for (int c = 0; c < 32; ++c) {
        float x = s[(size_t)c * N + n];
        float y = t[(size_t)c * N + m];
        dot = fmaf(x, y, dot);
        ns  = fmaf(x, x, ns);
        ng  = fmaf(y, y, ng);
    }
    return dot / (fmaxf(sqrtf(ns), 1e-8f) * fmaxf(sqrtf(ng), 1e-8f));
}

// grid 72: u<64 -> stage0 (b(4) x xb(16)); else stage1 (b(4) x xb(2))
__global__ void cos_kernel(const float* __restrict__ sd0, const float* __restrict__ td0,
                           const float* __restrict__ sd1, const float* __restrict__ td1,
                           float* __restrict__ out)
{
    __shared__ float wsum[TPB / 32];
    int u = blockIdx.x;
    int stage = (u < 64) ? 0 : 1;
    float cv;
    if (stage == 0) cv = cos_body<4096>(sd0, td0, g_k0, u & 3, u >> 2);
    else            cv = cos_body<512> (sd1, td1, g_k1, (u - 64) & 3, (u - 64) >> 2);

    for (int o = 16; o > 0; o >>= 1) cv += __shfl_down_sync(0xffffffffu, cv, o);
    if ((threadIdx.x & 31) == 0) wsum[threadIdx.x >> 5] = cv;
    __syncthreads();
    if (threadIdx.x < TPB / 32) {
        float v = wsum[threadIdx.x];
        for (int o = (TPB / 64); o > 0; o >>= 1) v += __shfl_down_sync(0xffu, v, o);
        if (threadIdx.x == 0) {
            atomicAdd(&g_acc[stage], (double)v);
            __threadfence();
            if (atomicAdd(&g_done, 1u) == 71u) {          // last cos block
                double a0 = atomicAdd(&g_acc[0], 0.0);
                double a1 = atomicAdd(&g_acc[1], 0.0);
                double l0 = 1.0 - a0 / (4.0 * 4096.0);
                double l1 = 1.0 - a1 / (4.0 * 512.0);
                out[0] = (float)(0.5 * (l0 + l1));
            }
        }
    }
}

// ---------------- launch (3 kernel launches) -------------------------------------
extern "C" void kernel_launch(void* const* d_in, const int* in_sizes, int n_in,
                              void* d_out, int out_size)
{
    const float* cs  = (const float*)d_in[0];  // canonical_source [4,3,64,64,64]
    const float* ct  = (const float*)d_in[1];  // canonical_target
    const float* sd0 = (const float*)d_in[2];  // src_desc0 [4,32,16,16,16]
    const float* td0 = (const float*)d_in[3];
    const float* sd1 = (const float*)d_in[4];  // src_desc1 [4,32,8,8,8]
    const float* td1 = (const float*)d_in[5];
    float* out = (float*)d_out;

    resize_kernel<<<NBLK, TPB>>>(cs, ct);
    nn_kernel<<<544, TPB>>>();
    cos_kernel<<<72, TPB>>>(sd0, td0, sd1, td1, out);
}